// round 13
// baseline (speedup 1.0000x reference)
#include <cuda_runtime.h>

#define PI_F 3.14159265358979f

// -------- scratch (no device allocations allowed) --------
__device__ float4 g_AB[512 * 4096];      // per (h,d): (alpha, beta) per m (bit-rev order), 33.6 MB
__device__ float  g_xt[64 * 64 * 4096];  // [bh][d][t] transposed x / y (in-place), 67 MB

static __device__ __forceinline__ int pidx(int n) { return n + (n >> 4); }
#define SMEM_CNT 4352   /* pidx(4095)=4350, K1 only */

// K3 XOR swizzle: permutes low 4 bits by bits [3:6]; conflict-free for all K3
// half-warp patterns (stride-512/64 consecutive-w, (blk,w) round, 8-consecutive
// round, mid) — verified per-pattern mod-16 injectivity.
static __device__ __forceinline__ int sidx(int n) { return n ^ ((n >> 3) & 15); }

// ---- packed f32x2 helpers (Blackwell) ----
union F2U { float2 f; unsigned long long u; };

static __device__ __forceinline__ float2 cadd(float2 a, float2 b) {
    F2U x, y, r; x.f = a; y.f = b;
    asm("add.rn.f32x2 %0, %1, %2;" : "=l"(r.u) : "l"(x.u), "l"(y.u));
    return r.f;
}
static __device__ __forceinline__ float2 csub(float2 a, float2 b) {
    F2U x, y, r; x.f = a; y.f = b;
    const unsigned long long NEG1 = 0xBF800000BF800000ULL;
    asm("fma.rn.f32x2 %0, %1, %2, %3;" : "=l"(r.u) : "l"(y.u), "l"(NEG1), "l"(x.u));
    return r.f;
}
static __device__ __forceinline__ float2 cmul(float2 a, float2 b) {
    return make_float2(fmaf(a.x, b.x, -a.y * b.y), fmaf(a.x, b.y, a.y * b.x));
}
static __device__ __forceinline__ float2 cconj(float2 a) { return make_float2(a.x, -a.y); }

// exp(SGN * i * pi * k / 8), k = 0..7  (K1 radix-16 round)
template <int SGN>
static __device__ __forceinline__ float2 rt16(int k) {
    const float C[8] = {1.f, 0.92387953251f, 0.70710678119f, 0.38268343236f,
                        0.f, -0.38268343236f, -0.70710678119f, -0.92387953251f};
    const float S[8] = {0.f, 0.38268343236f, 0.70710678119f, 0.92387953251f,
                        1.f, 0.92387953251f, 0.70710678119f, 0.38268343236f};
    return make_float2(C[k], (float)SGN * S[k]);
}

// exp(SGN * i * pi * k / 4), k = 0..3  (K3 radix-8 round)
template <int SGN>
static __device__ __forceinline__ float2 rt8(int k) {
    const float R = 0.70710678118654752f;
    const float C[4] = {1.f, R, 0.f, -R};
    const float S[4] = {0.f, R, 1.f, R};
    return make_float2(C[k], (float)SGN * S[k]);
}

// ---- radix-16 round (K1 only, R4-proven) ----
template <int SGN, bool TRIV, bool FIRSTZ = false, bool LASTHALF = false>
static __device__ __forceinline__ void fft_round(float2 r[16], float ang) {
    float2 b1;
    if (TRIV) {
        b1 = make_float2(1.f, 0.f);
    } else {
        float sv, cv;
        __sincosf(ang, &sv, &cv);
        b1 = make_float2(cv, SGN < 0 ? -sv : sv);
    }
    float2 b2 = cmul(b1, b1), b4 = cmul(b2, b2), b8 = cmul(b4, b4);
    float2 tw8[8], tw4[4], tw2[2];
#pragma unroll
    for (int k = 0; k < 8; k++) tw8[k] = cmul(b1, rt16<SGN>(k));
#pragma unroll
    for (int k = 0; k < 4; k++) tw4[k] = cmul(b2, rt16<SGN>(2 * k));
    tw2[0] = b4;
    tw2[1] = cmul(b4, make_float2(0.f, (float)SGN));
    if (SGN < 0) {
        if (FIRSTZ) {
#pragma unroll
            for (int k = 0; k < 8; k++) { float2 u = r[k]; r[k + 8] = cmul(u, tw8[k]); }
        } else {
#pragma unroll
            for (int k = 0; k < 8; k++) { float2 u = r[k], v = r[k + 8]; r[k] = cadd(u, v); r[k + 8] = cmul(csub(u, v), tw8[k]); }
        }
#pragma unroll
        for (int g = 0; g < 16; g += 8)
#pragma unroll
            for (int c = 0; c < 4; c++) { int a = g + c; float2 u = r[a], v = r[a + 4]; r[a] = cadd(u, v); r[a + 4] = cmul(csub(u, v), tw4[c]); }
#pragma unroll
        for (int g = 0; g < 16; g += 4)
#pragma unroll
            for (int c = 0; c < 2; c++) { int a = g + c; float2 u = r[a], v = r[a + 2]; r[a] = cadd(u, v); r[a + 2] = cmul(csub(u, v), tw2[c]); }
#pragma unroll
        for (int a = 0; a < 16; a += 2) { float2 u = r[a], v = r[a + 1]; r[a] = cadd(u, v); r[a + 1] = cmul(csub(u, v), b8); }
    } else {
#pragma unroll
        for (int a = 0; a < 16; a += 2) { float2 v = cmul(r[a + 1], b8), u = r[a]; r[a] = cadd(u, v); r[a + 1] = csub(u, v); }
#pragma unroll
        for (int g = 0; g < 16; g += 4)
#pragma unroll
            for (int c = 0; c < 2; c++) { int a = g + c; float2 v = cmul(r[a + 2], tw2[c]), u = r[a]; r[a] = cadd(u, v); r[a + 2] = csub(u, v); }
#pragma unroll
        for (int g = 0; g < 16; g += 8)
#pragma unroll
            for (int c = 0; c < 4; c++) { int a = g + c; float2 v = cmul(r[a + 4], tw4[c]), u = r[a]; r[a] = cadd(u, v); r[a + 4] = csub(u, v); }
#pragma unroll
        for (int k = 0; k < 8; k++) {
            float2 v = cmul(r[k + 8], tw8[k]), u = r[k];
            r[k] = cadd(u, v);
            if (!LASTHALF) r[k + 8] = csub(u, v);
        }
    }
}

// ---- radix-8 round (K3): 3 radix-2 stages on 8 elements ----
// Forward (SGN=-1) spans (4,2,1)*stride; inverse mirrored. TRIV: base = 1.
// FIRSTZ (fwd): r[4..7] zero on entry. LASTHALF (inv): only r[0..3] needed.
template <int SGN, bool TRIV, bool FIRSTZ = false, bool LASTHALF = false>
static __device__ __forceinline__ void fft8_round(float2 r[8], float ang) {
    float2 b1;
    if (TRIV) {
        b1 = make_float2(1.f, 0.f);
    } else {
        float sv, cv;
        __sincosf(ang, &sv, &cv);
        b1 = make_float2(cv, SGN < 0 ? -sv : sv);
    }
    float2 b2 = cmul(b1, b1), b4 = cmul(b2, b2);
    float2 twA[4], twB[2];
#pragma unroll
    for (int k = 0; k < 4; k++) twA[k] = TRIV ? rt8<SGN>(k) : cmul(b1, rt8<SGN>(k));
    twB[0] = b2;
    twB[1] = TRIV ? make_float2(0.f, (float)SGN) : cmul(b2, make_float2(0.f, (float)SGN));
    if (SGN < 0) {
        if (FIRSTZ) {
#pragma unroll
            for (int k = 0; k < 4; k++) r[k + 4] = cmul(r[k], twA[k]);
        } else {
#pragma unroll
            for (int k = 0; k < 4; k++) { float2 u = r[k], v = r[k + 4]; r[k] = cadd(u, v); r[k + 4] = cmul(csub(u, v), twA[k]); }
        }
#pragma unroll
        for (int g = 0; g < 8; g += 4)
#pragma unroll
            for (int c = 0; c < 2; c++) { int a = g + c; float2 u = r[a], v = r[a + 2]; r[a] = cadd(u, v); r[a + 2] = cmul(csub(u, v), twB[c]); }
#pragma unroll
        for (int a = 0; a < 8; a += 2) { float2 u = r[a], v = r[a + 1]; r[a] = cadd(u, v); r[a + 1] = cmul(csub(u, v), b4); }
    } else {
#pragma unroll
        for (int a = 0; a < 8; a += 2) { float2 v = cmul(r[a + 1], b4), u = r[a]; r[a] = cadd(u, v); r[a + 1] = csub(u, v); }
#pragma unroll
        for (int g = 0; g < 8; g += 4)
#pragma unroll
            for (int c = 0; c < 2; c++) { int a = g + c; float2 v = cmul(r[a + 2], twB[c]), u = r[a]; r[a] = cadd(u, v); r[a + 2] = csub(u, v); }
#pragma unroll
        for (int k = 0; k < 4; k++) {
            float2 v = cmul(r[k + 4], twA[k]), u = r[k];
            r[k] = cadd(u, v);
            if (!LASTHALF) r[k + 4] = csub(u, v);
        }
    }
}

// ---------------- K1: (alpha, beta) table per (h, d), natural order (unchanged) ----------------
__global__ __launch_bounds__(256) void k1_spectra(const float* __restrict__ zero,
                                                  const float* __restrict__ pos,
                                                  const float* __restrict__ gamma) {
    __shared__ float2 sm[SMEM_CNT];
    int tid = threadIdx.x;
    int ch = blockIdx.x;          // h*64 + d
    int h = ch >> 6, d = ch & 63;
    float lg = logf(gamma[ch]);
    float e0 = expf(fminf(fmaxf(zero[ch], -60.f), 30.f));

    float2 r[16];
#pragma unroll
    for (int k = 0; k < 16; k++) {
        int m = tid + 256 * k;
        float v0 = 0.f, v1 = 0.f;
        if (k < 8) {
            int t0 = 2 * m, t1 = 2 * m + 1;
            if (t0 == 0) v0 = e0;
            else {
                float p = pos[((size_t)h * 4095 + (t0 - 1)) * 64 + d];
                v0 = expf(fminf(fmaxf(fmaf((float)t0, lg, p), -60.f), 30.f));
            }
            if (t1 <= 4095) {
                float p = pos[((size_t)h * 4095 + (t1 - 1)) * 64 + d];
                v1 = expf(fminf(fmaxf(fmaf((float)t1, lg, p), -60.f), 30.f));
            }
        } else if (m == 2048) {
            v0 = e0;  // a[4096] = exp(clip(zero))
        }
        r[k] = make_float2(v0, v1);
    }

    fft_round<-1, false>(r, PI_F * (1.0f / 2048.0f) * (float)tid);
#pragma unroll
    for (int k = 0; k < 16; k++) sm[pidx(tid + 256 * k)] = r[k];
    __syncthreads();
    {
        int w = tid & 15, blk = tid >> 4;
#pragma unroll
        for (int k = 0; k < 16; k++) r[k] = sm[pidx(blk * 256 + w + 16 * k)];
        fft_round<-1, false>(r, PI_F * (1.0f / 128.0f) * (float)w);
#pragma unroll
        for (int k = 0; k < 16; k++) sm[pidx(blk * 256 + w + 16 * k)] = r[k];
    }
    __syncthreads();
#pragma unroll
    for (int k = 0; k < 16; k++) r[k] = sm[pidx(tid * 16 + k)];
    fft_round<-1, true>(r, 0.f);
#pragma unroll
    for (int k = 0; k < 16; k++) sm[pidx(tid * 16 + k)] = r[k];
    __syncthreads();

    const float sc = 1.0f / 32768.0f;
    float2 ar[16];
    float anyq = 0.f;
#pragma unroll
    for (int k = 0; k < 16; k++) {
        int m = tid + 256 * k;
        int kf = __brev(m) >> 20;
        int mp = __brev((4096 - kf) & 4095) >> 20;
        float2 Zm = sm[pidx(m)], Zp = sm[pidx(mp)];
        float2 S = cadd(Zm, cconj(Zp));
        float2 D = csub(Zm, cconj(Zp));
        float sw, cw;
        __sincosf(PI_F * (1.0f / 4096.0f) * (float)kf, &sw, &cw);
        float2 W = make_float2(cw, -sw);
        float2 T = cmul(W, D);
        float2 T2 = make_float2(T.y, -T.x);       // -i*W*D
        float2 Vlo = cadd(S, T2);                 // = 2*A[kf]
        ar[k] = make_float2(Vlo.x * sc, Vlo.y * sc);
        if (m == 0) {
            float2 Vhi = csub(S, T2);             // = 2*A[4096] (real)
            anyq = Vhi.x * sc;
        }
    }
    __syncthreads();
#pragma unroll
    for (int k = 0; k < 16; k++) sm[pidx(tid + 256 * k)] = ar[k];
    __syncthreads();

    float4* ab = g_AB + (size_t)ch * 4096;
#pragma unroll
    for (int k = 0; k < 16; k++) {
        int m = tid + 256 * k;
        int kf = __brev(m) >> 20;
        int mp = __brev((4096 - kf) & 4095) >> 20;
        float2 Alo = sm[pidx(m)];
        float2 Ahi = (m == 0) ? make_float2(anyq, 0.f) : cconj(sm[pidx(mp)]);
        float sw, cw;
        __sincosf(PI_F * (1.0f / 4096.0f) * (float)kf, &sw, &cw);
        float ca = 2.f - 2.f * sw, cb = 2.f + 2.f * sw, cc = 2.f * cw;
        float2 alpha = make_float2(ca * Alo.x + cb * Ahi.x, ca * Alo.y + cb * Ahi.y);
        float2 dif = csub(Alo, Ahi);
        float2 beta = make_float2(-cc * dif.y, cc * dif.x);
        ab[m] = make_float4(alpha.x, alpha.y, beta.x, beta.y);
    }
}

// ---------------- K2: x [bh][t][d] -> g_xt [bh][d][t], 64x64 float4 tiles ----------------
__global__ __launch_bounds__(256) void k2_transpose(const float* __restrict__ x, int bh0) {
    __shared__ float tile[64][65];
    int bh = bh0 + blockIdx.y;
    int t0 = blockIdx.x << 6;
    const float4* xp4 = (const float4*)(x + (size_t)bh * (4096 * 64));
    float4* xtp4 = (float4*)(g_xt + (size_t)bh * (64 * 4096));
    int tx = threadIdx.x & 15, ty = threadIdx.x >> 4;
#pragma unroll
    for (int j = 0; j < 4; j++) {
        int t = ty + 16 * j;
        float4 v = xp4[(size_t)(t0 + t) * 16 + tx];
        tile[t][4 * tx + 0] = v.x; tile[t][4 * tx + 1] = v.y;
        tile[t][4 * tx + 2] = v.z; tile[t][4 * tx + 3] = v.w;
    }
    __syncthreads();
#pragma unroll
    for (int j = 0; j < 4; j++) {
        int d = ty + 16 * j;
        float4 v = make_float4(tile[4 * tx + 0][d], tile[4 * tx + 1][d],
                               tile[4 * tx + 2][d], tile[4 * tx + 3][d]);
        xtp4[(size_t)d * 1024 + (t0 >> 2) + tx] = v;
    }
}

// ---------------- K3: radix-8, 512 threads, XOR-swizzled smem, 2 CTAs/SM ----------------
__global__ __launch_bounds__(512, 2) void k3_fftconv(int b0) {
    __shared__ float2 sm[4096];
    int tid = threadIdx.x;
    int idx = blockIdx.x;
    int b  = b0 + (idx & 3);
    int hd = idx >> 2;                 // ch = h*64 + d
    int bhd = (b * 8 + (hd >> 6)) * 64 + (hd & 63);
    float2* row = (float2*)(g_xt + (size_t)bhd * 4096);

    float2 r[8];
#pragma unroll
    for (int k = 0; k < 4; k++) r[k] = row[tid + 512 * k];      // z[m]=u[2m]+i u[2m+1]
#pragma unroll
    for (int k = 4; k < 8; k++) r[k] = make_float2(0.f, 0.f);   // zero padding

    // fwd round 1: spans 2048,1024,512; FIRSTZ
    fft8_round<-1, false, true>(r, PI_F * (1.0f / 2048.0f) * (float)tid);
#pragma unroll
    for (int k = 0; k < 8; k++) sm[sidx(tid + 512 * k)] = r[k];
    __syncthreads();
    // fwd round 2: spans 256,128,64
    int w2 = tid & 63, blk2 = tid >> 6;
#pragma unroll
    for (int k = 0; k < 8; k++) r[k] = sm[sidx(blk2 * 512 + w2 + 64 * k)];
    fft8_round<-1, false>(r, PI_F * (1.0f / 256.0f) * (float)w2);
#pragma unroll
    for (int k = 0; k < 8; k++) sm[sidx(blk2 * 512 + w2 + 64 * k)] = r[k];
    __syncthreads();
    // fwd round 3: spans 32,16,8
    int w3 = tid & 7, blk3 = tid >> 3;
#pragma unroll
    for (int k = 0; k < 8; k++) r[k] = sm[sidx(blk3 * 64 + w3 + 8 * k)];
    fft8_round<-1, false>(r, PI_F * (1.0f / 32.0f) * (float)w3);
#pragma unroll
    for (int k = 0; k < 8; k++) sm[sidx(blk3 * 64 + w3 + 8 * k)] = r[k];
    __syncthreads();
    // fwd round 4: spans 4,2,1 (TRIV), own 8-block in place
#pragma unroll
    for (int j = 0; j < 8; j++) r[j] = sm[sidx(8 * tid + j)];
    fft8_round<-1, true>(r, 0.f);
#pragma unroll
    for (int j = 0; j < 8; j++) sm[sidx(8 * tid + j)] = r[j];
    __syncthreads();

    // MID: Z'[m] = alpha*Z[m] + beta*conj(Z[mp]); AB natural-coalesced
    const float4* abp = g_AB + (size_t)hd * 4096;
#pragma unroll
    for (int k = 0; k < 8; k++) {
        int m = tid + 512 * k;
        int kf = __brev(m) >> 20;
        int mp = __brev((4096 - kf) & 4095) >> 20;
        float2 Zm = sm[sidx(m)], Zp = sm[sidx(mp)];
        float4 ab = abp[m];
        float2 t1 = cmul(Zm, make_float2(ab.x, ab.y));
        float2 t2 = cmul(cconj(Zp), make_float2(ab.z, ab.w));
        r[k] = cadd(t1, t2);
    }
    __syncthreads();
#pragma unroll
    for (int k = 0; k < 8; k++) sm[sidx(tid + 512 * k)] = r[k];
    __syncthreads();

    // inverse round 4' (TRIV), own 8-block in place
#pragma unroll
    for (int j = 0; j < 8; j++) r[j] = sm[sidx(8 * tid + j)];
    fft8_round<1, true>(r, 0.f);
#pragma unroll
    for (int j = 0; j < 8; j++) sm[sidx(8 * tid + j)] = r[j];
    __syncthreads();
    // inverse round 3'
#pragma unroll
    for (int k = 0; k < 8; k++) r[k] = sm[sidx(blk3 * 64 + w3 + 8 * k)];
    fft8_round<1, false>(r, PI_F * (1.0f / 32.0f) * (float)w3);
#pragma unroll
    for (int k = 0; k < 8; k++) sm[sidx(blk3 * 64 + w3 + 8 * k)] = r[k];
    __syncthreads();
    // inverse round 2'
#pragma unroll
    for (int k = 0; k < 8; k++) r[k] = sm[sidx(blk2 * 512 + w2 + 64 * k)];
    fft8_round<1, false>(r, PI_F * (1.0f / 256.0f) * (float)w2);
#pragma unroll
    for (int k = 0; k < 8; k++) sm[sidx(blk2 * 512 + w2 + 64 * k)] = r[k];
    __syncthreads();
    // inverse round 1' (LASTHALF): keep t < 4096 only
#pragma unroll
    for (int k = 0; k < 8; k++) r[k] = sm[sidx(tid + 512 * k)];
    fft8_round<1, false, false, true>(r, PI_F * (1.0f / 2048.0f) * (float)tid);
#pragma unroll
    for (int k = 0; k < 4; k++) row[tid + 512 * k] = r[k];
}

// ---------------- K4: g_xt (y) [bh][d][t] -> out [bh][t][d], 64x64 float4 tiles ----------------
__global__ __launch_bounds__(256) void k4_transpose(float* __restrict__ out, int bh0) {
    __shared__ float tile[64][65];
    int bh = bh0 + blockIdx.y;
    int t0 = blockIdx.x << 6;
    const float4* ytp4 = (const float4*)(g_xt + (size_t)bh * (64 * 4096));
    float4* op4 = (float4*)(out + (size_t)bh * (4096 * 64));
    int tx = threadIdx.x & 15, ty = threadIdx.x >> 4;
#pragma unroll
    for (int j = 0; j < 4; j++) {
        int d = ty + 16 * j;
        float4 v = ytp4[(size_t)d * 1024 + (t0 >> 2) + tx];
        tile[4 * tx + 0][d] = v.x; tile[4 * tx + 1][d] = v.y;
        tile[4 * tx + 2][d] = v.z; tile[4 * tx + 3][d] = v.w;
    }
    __syncthreads();
#pragma unroll
    for (int j = 0; j < 4; j++) {
        int t = ty + 16 * j;
        float4 v = make_float4(tile[t][4 * tx + 0], tile[t][4 * tx + 1],
                               tile[t][4 * tx + 2], tile[t][4 * tx + 3]);
        op4[(size_t)(t0 + t) * 16 + tx] = v;
    }
}

// ---- streams/events for pipelined graph topology ----
static cudaStream_t g_s2 = 0, g_s3 = 0;
static cudaEvent_t g_evRoot = 0, g_evK1 = 0, g_evK3a = 0, g_evK3b = 0;
static bool g_ok = false;
static struct StreamInit {
    StreamInit() {
        bool ok = true;
        ok &= cudaStreamCreateWithFlags(&g_s2, cudaStreamNonBlocking) == cudaSuccess;
        ok &= cudaStreamCreateWithFlags(&g_s3, cudaStreamNonBlocking) == cudaSuccess;
        ok &= cudaEventCreateWithFlags(&g_evRoot, cudaEventDisableTiming) == cudaSuccess;
        ok &= cudaEventCreateWithFlags(&g_evK1, cudaEventDisableTiming) == cudaSuccess;
        ok &= cudaEventCreateWithFlags(&g_evK3a, cudaEventDisableTiming) == cudaSuccess;
        ok &= cudaEventCreateWithFlags(&g_evK3b, cudaEventDisableTiming) == cudaSuccess;
        g_ok = ok;
    }
} g_stream_init;

extern "C" void kernel_launch(void* const* d_in, const int* in_sizes, int n_in,
                              void* d_out, int out_size) {
    (void)in_sizes; (void)n_in; (void)out_size;
    const float* x     = (const float*)d_in[0];
    const float* zero  = (const float*)d_in[1];
    const float* pos   = (const float*)d_in[2];
    const float* gamma = (const float*)d_in[3];
    float* out = (float*)d_out;

    if (g_ok) {
        cudaEventRecord(g_evRoot, 0);
        cudaStreamWaitEvent(g_s2, g_evRoot, 0);
        cudaStreamWaitEvent(g_s3, g_evRoot, 0);

        k1_spectra<<<512, 256, 0, g_s2>>>(zero, pos, gamma);
        cudaEventRecord(g_evK1, g_s2);

        k2_transpose<<<dim3(64, 32), 256, 0, g_s3>>>(x, 32);   // bh 32..63
        k2_transpose<<<dim3(64, 32), 256>>>(x, 0);             // bh 0..31

        cudaStreamWaitEvent(0, g_evK1, 0);
        k3_fftconv<<<2048, 512>>>(0);                          // b 0..3
        cudaEventRecord(g_evK3a, 0);

        cudaStreamWaitEvent(g_s3, g_evK1, 0);
        cudaStreamWaitEvent(g_s3, g_evK3a, 0);
        k3_fftconv<<<2048, 512, 0, g_s3>>>(4);                 // b 4..7
        cudaEventRecord(g_evK3b, g_s3);

        k4_transpose<<<dim3(64, 32), 256>>>(out, 0);           // overlaps K3b

        cudaStreamWaitEvent(0, g_evK3b, 0);
        k4_transpose<<<dim3(64, 32), 256>>>(out, 32);
    } else {
        k1_spectra<<<512, 256>>>(zero, pos, gamma);
        k2_transpose<<<dim3(64, 32), 256>>>(x, 0);
        k2_transpose<<<dim3(64, 32), 256>>>(x, 32);
        k3_fftconv<<<2048, 512>>>(0);
        k3_fftconv<<<2048, 512>>>(4);
        k4_transpose<<<dim3(64, 32), 256>>>(out, 0);
        k4_transpose<<<dim3(64, 32), 256>>>(out, 32);
    }
}

// round 14
// speedup vs baseline: 1.1454x; 1.1454x over previous
#include <cuda_runtime.h>

#define PI_F 3.14159265358979f

// -------- scratch (no device allocations allowed) --------
__device__ float4 g_AB[512 * 4096];      // per (h,d): (alpha, beta) per m (bit-rev order), 33.6 MB
__device__ float  g_xt[64 * 64 * 4096];  // [bh][d][t] transposed x / y (in-place), 67 MB

static __device__ __forceinline__ int pidx(int n) { return n + (n >> 4); }
#define SMEM_CNT 4352   /* pidx(4095)=4350 */

// ---- packed f32x2 helpers (Blackwell) ----
union F2U { float2 f; unsigned long long u; };

static __device__ __forceinline__ float2 cadd(float2 a, float2 b) {
    F2U x, y, r; x.f = a; y.f = b;
    asm("add.rn.f32x2 %0, %1, %2;" : "=l"(r.u) : "l"(x.u), "l"(y.u));
    return r.f;
}
static __device__ __forceinline__ float2 csub(float2 a, float2 b) {
    F2U x, y, r; x.f = a; y.f = b;
    const unsigned long long NEG1 = 0xBF800000BF800000ULL;
    asm("fma.rn.f32x2 %0, %1, %2, %3;" : "=l"(r.u) : "l"(y.u), "l"(NEG1), "l"(x.u));
    return r.f;
}
static __device__ __forceinline__ float2 cmul(float2 a, float2 b) {
    return make_float2(fmaf(a.x, b.x, -a.y * b.y), fmaf(a.x, b.y, a.y * b.x));
}
static __device__ __forceinline__ float2 cconj(float2 a) { return make_float2(a.x, -a.y); }

// exp(SGN * i * pi * k / 8), k = 0..7
template <int SGN>
static __device__ __forceinline__ float2 rt16(int k) {
    const float C[8] = {1.f, 0.92387953251f, 0.70710678119f, 0.38268343236f,
                        0.f, -0.38268343236f, -0.70710678119f, -0.92387953251f};
    const float S[8] = {0.f, 0.38268343236f, 0.70710678119f, 0.92387953251f,
                        1.f, 0.92387953251f, 0.70710678119f, 0.38268343236f};
    return make_float2(C[k], (float)SGN * S[k]);
}

// One register round of 4 radix-2 stages on 16 elements (R4-proven structure).
// TRIV: twiddle base = 1. FIRSTZ (fwd): r[8..15] zero on entry. LASTHALF (inv):
// only r[0..7] outputs needed.
template <int SGN, bool TRIV, bool FIRSTZ = false, bool LASTHALF = false>
static __device__ __forceinline__ void fft_round(float2 r[16], float ang) {
    float2 b1;
    if (TRIV) {
        b1 = make_float2(1.f, 0.f);
    } else {
        float sv, cv;
        __sincosf(ang, &sv, &cv);
        b1 = make_float2(cv, SGN < 0 ? -sv : sv);
    }
    float2 b2 = cmul(b1, b1), b4 = cmul(b2, b2), b8 = cmul(b4, b4);
    float2 tw8[8], tw4[4], tw2[2];
#pragma unroll
    for (int k = 0; k < 8; k++) tw8[k] = cmul(b1, rt16<SGN>(k));
#pragma unroll
    for (int k = 0; k < 4; k++) tw4[k] = cmul(b2, rt16<SGN>(2 * k));
    tw2[0] = b4;
    tw2[1] = cmul(b4, make_float2(0.f, (float)SGN));
    if (SGN < 0) {
        if (FIRSTZ) {
#pragma unroll
            for (int k = 0; k < 8; k++) { float2 u = r[k]; r[k + 8] = cmul(u, tw8[k]); }
        } else {
#pragma unroll
            for (int k = 0; k < 8; k++) { float2 u = r[k], v = r[k + 8]; r[k] = cadd(u, v); r[k + 8] = cmul(csub(u, v), tw8[k]); }
        }
#pragma unroll
        for (int g = 0; g < 16; g += 8)
#pragma unroll
            for (int c = 0; c < 4; c++) { int a = g + c; float2 u = r[a], v = r[a + 4]; r[a] = cadd(u, v); r[a + 4] = cmul(csub(u, v), tw4[c]); }
#pragma unroll
        for (int g = 0; g < 16; g += 4)
#pragma unroll
            for (int c = 0; c < 2; c++) { int a = g + c; float2 u = r[a], v = r[a + 2]; r[a] = cadd(u, v); r[a + 2] = cmul(csub(u, v), tw2[c]); }
#pragma unroll
        for (int a = 0; a < 16; a += 2) { float2 u = r[a], v = r[a + 1]; r[a] = cadd(u, v); r[a + 1] = cmul(csub(u, v), b8); }
    } else {
#pragma unroll
        for (int a = 0; a < 16; a += 2) { float2 v = cmul(r[a + 1], b8), u = r[a]; r[a] = cadd(u, v); r[a + 1] = csub(u, v); }
#pragma unroll
        for (int g = 0; g < 16; g += 4)
#pragma unroll
            for (int c = 0; c < 2; c++) { int a = g + c; float2 v = cmul(r[a + 2], tw2[c]), u = r[a]; r[a] = cadd(u, v); r[a + 2] = csub(u, v); }
#pragma unroll
        for (int g = 0; g < 16; g += 8)
#pragma unroll
            for (int c = 0; c < 4; c++) { int a = g + c; float2 v = cmul(r[a + 4], tw4[c]), u = r[a]; r[a] = cadd(u, v); r[a + 4] = csub(u, v); }
#pragma unroll
        for (int k = 0; k < 8; k++) {
            float2 v = cmul(r[k + 8], tw8[k]), u = r[k];
            r[k] = cadd(u, v);
            if (!LASTHALF) r[k + 8] = csub(u, v);
        }
    }
}

// ---------------- K1: (alpha, beta) table per (h, d), natural order ----------------
__global__ __launch_bounds__(256) void k1_spectra(const float* __restrict__ zero,
                                                  const float* __restrict__ pos,
                                                  const float* __restrict__ gamma) {
    __shared__ float2 sm[SMEM_CNT];
    int tid = threadIdx.x;
    int ch = blockIdx.x;          // h*64 + d
    int h = ch >> 6, d = ch & 63;
    float lg = logf(gamma[ch]);
    float e0 = expf(fminf(fmaxf(zero[ch], -60.f), 30.f));

    float2 r[16];
#pragma unroll
    for (int k = 0; k < 16; k++) {
        int m = tid + 256 * k;
        float v0 = 0.f, v1 = 0.f;
        if (k < 8) {
            int t0 = 2 * m, t1 = 2 * m + 1;
            if (t0 == 0) v0 = e0;
            else {
                float p = pos[((size_t)h * 4095 + (t0 - 1)) * 64 + d];
                v0 = expf(fminf(fmaxf(fmaf((float)t0, lg, p), -60.f), 30.f));
            }
            if (t1 <= 4095) {
                float p = pos[((size_t)h * 4095 + (t1 - 1)) * 64 + d];
                v1 = expf(fminf(fmaxf(fmaf((float)t1, lg, p), -60.f), 30.f));
            }
        } else if (m == 2048) {
            v0 = e0;  // a[4096] = exp(clip(zero))
        }
        r[k] = make_float2(v0, v1);
    }

    // forward 4096-pt FFT (natural -> bit-rev)
    fft_round<-1, false>(r, PI_F * (1.0f / 2048.0f) * (float)tid);
#pragma unroll
    for (int k = 0; k < 16; k++) sm[pidx(tid + 256 * k)] = r[k];
    __syncthreads();
    {
        int w = tid & 15, blk = tid >> 4;
#pragma unroll
        for (int k = 0; k < 16; k++) r[k] = sm[pidx(blk * 256 + w + 16 * k)];
        fft_round<-1, false>(r, PI_F * (1.0f / 128.0f) * (float)w);
#pragma unroll
        for (int k = 0; k < 16; k++) sm[pidx(blk * 256 + w + 16 * k)] = r[k];
    }
    __syncthreads();
#pragma unroll
    for (int k = 0; k < 16; k++) r[k] = sm[pidx(tid * 16 + k)];
    fft_round<-1, true>(r, 0.f);
#pragma unroll
    for (int k = 0; k < 16; k++) sm[pidx(tid * 16 + k)] = r[k];
    __syncthreads();

    // Unpack real-FFT: A[kf], scaled by 1/32768; keep Nyquist locally (thread m==0).
    const float sc = 1.0f / 32768.0f;
    float2 ar[16];
    float anyq = 0.f;
#pragma unroll
    for (int k = 0; k < 16; k++) {
        int m = tid + 256 * k;
        int kf = __brev(m) >> 20;
        int mp = __brev((4096 - kf) & 4095) >> 20;
        float2 Zm = sm[pidx(m)], Zp = sm[pidx(mp)];
        float2 S = cadd(Zm, cconj(Zp));
        float2 D = csub(Zm, cconj(Zp));
        float sw, cw;
        __sincosf(PI_F * (1.0f / 4096.0f) * (float)kf, &sw, &cw);
        float2 W = make_float2(cw, -sw);
        float2 T = cmul(W, D);
        float2 T2 = make_float2(T.y, -T.x);       // -i*W*D
        float2 Vlo = cadd(S, T2);                 // = 2*A[kf]
        ar[k] = make_float2(Vlo.x * sc, Vlo.y * sc);
        if (m == 0) {
            float2 Vhi = csub(S, T2);             // = 2*A[4096] (real)
            anyq = Vhi.x * sc;
        }
    }
    __syncthreads();
#pragma unroll
    for (int k = 0; k < 16; k++) sm[pidx(tid + 256 * k)] = ar[k];
    __syncthreads();

    // alpha/beta: Z'[m] = alpha*Z[m] + beta*conj(Z[mp]); natural ab[m] (coalesced).
    float4* ab = g_AB + (size_t)ch * 4096;
#pragma unroll
    for (int k = 0; k < 16; k++) {
        int m = tid + 256 * k;
        int kf = __brev(m) >> 20;
        int mp = __brev((4096 - kf) & 4095) >> 20;
        float2 Alo = sm[pidx(m)];
        float2 Ahi = (m == 0) ? make_float2(anyq, 0.f) : cconj(sm[pidx(mp)]);
        float sw, cw;
        __sincosf(PI_F * (1.0f / 4096.0f) * (float)kf, &sw, &cw);
        float ca = 2.f - 2.f * sw, cb = 2.f + 2.f * sw, cc = 2.f * cw;
        float2 alpha = make_float2(ca * Alo.x + cb * Ahi.x, ca * Alo.y + cb * Ahi.y);
        float2 dif = csub(Alo, Ahi);
        float2 beta = make_float2(-cc * dif.y, cc * dif.x);
        ab[m] = make_float4(alpha.x, alpha.y, beta.x, beta.y);
    }
}

// ---------------- K2: x [bh][t][d] -> g_xt [bh][d][t], 64x64 float4 tiles ----------------
__global__ __launch_bounds__(256) void k2_transpose(const float* __restrict__ x, int bh0) {
    __shared__ float tile[64][65];
    int bh = bh0 + blockIdx.y;
    int t0 = blockIdx.x << 6;
    const float4* xp4 = (const float4*)(x + (size_t)bh * (4096 * 64));
    float4* xtp4 = (float4*)(g_xt + (size_t)bh * (64 * 4096));
    int tx = threadIdx.x & 15, ty = threadIdx.x >> 4;
#pragma unroll
    for (int j = 0; j < 4; j++) {
        int t = ty + 16 * j;
        float4 v = xp4[(size_t)(t0 + t) * 16 + tx];
        tile[t][4 * tx + 0] = v.x; tile[t][4 * tx + 1] = v.y;
        tile[t][4 * tx + 2] = v.z; tile[t][4 * tx + 3] = v.w;
    }
    __syncthreads();
#pragma unroll
    for (int j = 0; j < 4; j++) {
        int d = ty + 16 * j;
        float4 v = make_float4(tile[4 * tx + 0][d], tile[4 * tx + 1][d],
                               tile[4 * tx + 2][d], tile[4 * tx + 3][d]);
        xtp4[(size_t)d * 1024 + (t0 >> 2) + tx] = v;
    }
}

// ---------------- K3: per (b, h, d) real FFT conv; batches [b0, b0+2); hd-major for AB L2 reuse ----------------
__global__ __launch_bounds__(256, 3) void k3_fftconv(int b0) {
    __shared__ float2 sm[SMEM_CNT];
    int tid = threadIdx.x;
    // idx = hd*2 + (b - b0): 2 batch-blocks sharing one AB row are adjacent.
    int idx = blockIdx.x;
    int b  = b0 + (idx & 1);
    int hd = idx >> 1;                 // ch = h*64 + d
    int bhd = (b * 8 + (hd >> 6)) * 64 + (hd & 63);
    float2* row = (float2*)(g_xt + (size_t)bhd * 4096);

    float2 r[16];
#pragma unroll
    for (int k = 0; k < 8; k++) r[k] = row[tid + 256 * k];      // z[m]=u[2m]+i u[2m+1]
#pragma unroll
    for (int k = 8; k < 16; k++) r[k] = make_float2(0.f, 0.f);  // zero padding

    // forward rounds (round 1 exploits zero upper half)
    fft_round<-1, false, true>(r, PI_F * (1.0f / 2048.0f) * (float)tid);
#pragma unroll
    for (int k = 0; k < 16; k++) sm[pidx(tid + 256 * k)] = r[k];
    __syncthreads();
    int w = tid & 15, blk = tid >> 4;
#pragma unroll
    for (int k = 0; k < 16; k++) r[k] = sm[pidx(blk * 256 + w + 16 * k)];
    fft_round<-1, false>(r, PI_F * (1.0f / 128.0f) * (float)w);
#pragma unroll
    for (int k = 0; k < 16; k++) sm[pidx(blk * 256 + w + 16 * k)] = r[k];
    __syncthreads();
#pragma unroll
    for (int k = 0; k < 16; k++) r[k] = sm[pidx(tid * 16 + k)];
    fft_round<-1, true>(r, 0.f);
#pragma unroll
    for (int k = 0; k < 16; k++) sm[pidx(tid * 16 + k)] = r[k];
    __syncthreads();

    // MID: Z'[m] = alpha*Z[m] + beta*conj(Z[mp]); coalesced natural-order table reads.
    const float4* abp = g_AB + (size_t)hd * 4096;
#pragma unroll
    for (int k = 0; k < 16; k++) {
        int m = tid + 256 * k;
        int kf = __brev(m) >> 20;
        int mp = __brev((4096 - kf) & 4095) >> 20;
        float2 Zm = sm[pidx(m)], Zp = sm[pidx(mp)];
        float4 ab = abp[m];
        float2 t1 = cmul(Zm, make_float2(ab.x, ab.y));
        float2 t2 = cmul(cconj(Zp), make_float2(ab.z, ab.w));
        r[k] = cadd(t1, t2);
    }
    __syncthreads();
#pragma unroll
    for (int k = 0; k < 16; k++) sm[pidx(tid + 256 * k)] = r[k];
    __syncthreads();

    // Inverse DIT (bit-rev -> natural), mirrored rounds.
#pragma unroll
    for (int k = 0; k < 16; k++) r[k] = sm[pidx(tid * 16 + k)];
    fft_round<1, true>(r, 0.f);
#pragma unroll
    for (int k = 0; k < 16; k++) sm[pidx(tid * 16 + k)] = r[k];
    __syncthreads();
#pragma unroll
    for (int k = 0; k < 16; k++) r[k] = sm[pidx(blk * 256 + w + 16 * k)];
    fft_round<1, false>(r, PI_F * (1.0f / 128.0f) * (float)w);
#pragma unroll
    for (int k = 0; k < 16; k++) sm[pidx(blk * 256 + w + 16 * k)] = r[k];
    __syncthreads();
#pragma unroll
    for (int k = 0; k < 16; k++) r[k] = sm[pidx(tid + 256 * k)];
    fft_round<1, false, false, true>(r, PI_F * (1.0f / 2048.0f) * (float)tid);
#pragma unroll
    for (int k = 0; k < 8; k++) row[tid + 256 * k] = r[k];   // y[2m], y[2m+1]; t<4096 only
}

// ---------------- K4: g_xt (y) [bh][d][t] -> out [bh][t][d], 64x64 float4 tiles ----------------
__global__ __launch_bounds__(256) void k4_transpose(float* __restrict__ out, int bh0) {
    __shared__ float tile[64][65];
    int bh = bh0 + blockIdx.y;
    int t0 = blockIdx.x << 6;
    const float4* ytp4 = (const float4*)(g_xt + (size_t)bh * (64 * 4096));
    float4* op4 = (float4*)(out + (size_t)bh * (4096 * 64));
    int tx = threadIdx.x & 15, ty = threadIdx.x >> 4;
#pragma unroll
    for (int j = 0; j < 4; j++) {
        int d = ty + 16 * j;
        float4 v = ytp4[(size_t)d * 1024 + (t0 >> 2) + tx];
        tile[4 * tx + 0][d] = v.x; tile[4 * tx + 1][d] = v.y;
        tile[4 * tx + 2][d] = v.z; tile[4 * tx + 3][d] = v.w;
    }
    __syncthreads();
#pragma unroll
    for (int j = 0; j < 4; j++) {
        int t = ty + 16 * j;
        float4 v = make_float4(tile[t][4 * tx + 0], tile[t][4 * tx + 1],
                               tile[t][4 * tx + 2], tile[t][4 * tx + 3]);
        op4[(size_t)(t0 + t) * 16 + tx] = v;
    }
}

// ---- streams/events for 4-stage pipelined graph topology ----
static cudaStream_t g_s2 = 0, g_s3 = 0, g_s4 = 0;
static cudaEvent_t g_evRoot = 0, g_evK1 = 0, g_evK2[4] = {}, g_evK3[4] = {}, g_evK4 = 0;
static bool g_ok = false;
static struct StreamInit {
    StreamInit() {
        bool ok = true;
        ok &= cudaStreamCreateWithFlags(&g_s2, cudaStreamNonBlocking) == cudaSuccess;
        ok &= cudaStreamCreateWithFlags(&g_s3, cudaStreamNonBlocking) == cudaSuccess;
        ok &= cudaStreamCreateWithFlags(&g_s4, cudaStreamNonBlocking) == cudaSuccess;
        ok &= cudaEventCreateWithFlags(&g_evRoot, cudaEventDisableTiming) == cudaSuccess;
        ok &= cudaEventCreateWithFlags(&g_evK1, cudaEventDisableTiming) == cudaSuccess;
        for (int q = 0; q < 4; q++) {
            ok &= cudaEventCreateWithFlags(&g_evK2[q], cudaEventDisableTiming) == cudaSuccess;
            ok &= cudaEventCreateWithFlags(&g_evK3[q], cudaEventDisableTiming) == cudaSuccess;
        }
        ok &= cudaEventCreateWithFlags(&g_evK4, cudaEventDisableTiming) == cudaSuccess;
        g_ok = ok;
    }
} g_stream_init;

extern "C" void kernel_launch(void* const* d_in, const int* in_sizes, int n_in,
                              void* d_out, int out_size) {
    (void)in_sizes; (void)n_in; (void)out_size;
    const float* x     = (const float*)d_in[0];
    const float* zero  = (const float*)d_in[1];
    const float* pos   = (const float*)d_in[2];
    const float* gamma = (const float*)d_in[3];
    float* out = (float*)d_out;

    if (g_ok) {
        // 4-stage pipeline:
        //   s2: K1
        //   s3: K2 quarters (bh 16q..16q+15), event each
        //   0 : K3 quarters (b 2q..2q+1), waits evK1 + evK2[q], event each
        //   s4: K4 quarters, waits evK3[q]; joins back to 0 at the end
        cudaEventRecord(g_evRoot, 0);
        cudaStreamWaitEvent(g_s2, g_evRoot, 0);
        cudaStreamWaitEvent(g_s3, g_evRoot, 0);

        k1_spectra<<<512, 256, 0, g_s2>>>(zero, pos, gamma);
        cudaEventRecord(g_evK1, g_s2);

        for (int q = 0; q < 4; q++) {
            k2_transpose<<<dim3(64, 16), 256, 0, g_s3>>>(x, 16 * q);
            cudaEventRecord(g_evK2[q], g_s3);
        }

        cudaStreamWaitEvent(0, g_evK1, 0);
        for (int q = 0; q < 4; q++) {
            cudaStreamWaitEvent(0, g_evK2[q], 0);
            k3_fftconv<<<1024, 256>>>(2 * q);
            cudaEventRecord(g_evK3[q], 0);
        }

        for (int q = 0; q < 4; q++) {
            cudaStreamWaitEvent(g_s4, g_evK3[q], 0);
            k4_transpose<<<dim3(64, 16), 256, 0, g_s4>>>(out, 16 * q);
        }
        cudaEventRecord(g_evK4, g_s4);
        cudaStreamWaitEvent(0, g_evK4, 0);   // join s4 back into origin
    } else {
        // Fallback: serial topology (identical kernels/work).
        k1_spectra<<<512, 256>>>(zero, pos, gamma);
        for (int q = 0; q < 4; q++) k2_transpose<<<dim3(64, 16), 256>>>(x, 16 * q);
        for (int q = 0; q < 4; q++) k3_fftconv<<<1024, 256>>>(2 * q);
        for (int q = 0; q < 4; q++) k4_transpose<<<dim3(64, 16), 256>>>(out, 16 * q);
    }
}

// round 15
// speedup vs baseline: 1.2219x; 1.0668x over previous
#include <cuda_runtime.h>

#define PI_F 3.14159265358979f

// -------- scratch (no device allocations allowed) --------
__device__ float4 g_AB[512 * 4096];      // per (h,d): (alpha, beta) per m (bit-rev order), 33.6 MB
__device__ float  g_xt[64 * 64 * 4096];  // [bh][d][t] transposed x / y (in-place), 67 MB

static __device__ __forceinline__ int pidx(int n) { return n + (n >> 4); }
#define SMEM_CNT 4352   /* pidx(4095)=4350 */

// ---- packed f32x2 helpers (Blackwell) ----
union F2U { float2 f; unsigned long long u; };

static __device__ __forceinline__ float2 cadd(float2 a, float2 b) {
    F2U x, y, r; x.f = a; y.f = b;
    asm("add.rn.f32x2 %0, %1, %2;" : "=l"(r.u) : "l"(x.u), "l"(y.u));
    return r.f;
}
static __device__ __forceinline__ float2 csub(float2 a, float2 b) {
    F2U x, y, r; x.f = a; y.f = b;
    const unsigned long long NEG1 = 0xBF800000BF800000ULL;
    asm("fma.rn.f32x2 %0, %1, %2, %3;" : "=l"(r.u) : "l"(y.u), "l"(NEG1), "l"(x.u));
    return r.f;
}
static __device__ __forceinline__ float2 cmul(float2 a, float2 b) {
    return make_float2(fmaf(a.x, b.x, -a.y * b.y), fmaf(a.x, b.y, a.y * b.x));
}
static __device__ __forceinline__ float2 cconj(float2 a) { return make_float2(a.x, -a.y); }

// exp(SGN * i * pi * k / 8), k = 0..7
template <int SGN>
static __device__ __forceinline__ float2 rt16(int k) {
    const float C[8] = {1.f, 0.92387953251f, 0.70710678119f, 0.38268343236f,
                        0.f, -0.38268343236f, -0.70710678119f, -0.92387953251f};
    const float S[8] = {0.f, 0.38268343236f, 0.70710678119f, 0.92387953251f,
                        1.f, 0.92387953251f, 0.70710678119f, 0.38268343236f};
    return make_float2(C[k], (float)SGN * S[k]);
}

// One register round of 4 radix-2 stages on 16 elements (R4-proven structure).
// TRIV: twiddle base = 1. FIRSTZ (fwd): r[8..15] zero on entry. LASTHALF (inv):
// only r[0..7] outputs needed.
template <int SGN, bool TRIV, bool FIRSTZ = false, bool LASTHALF = false>
static __device__ __forceinline__ void fft_round(float2 r[16], float ang) {
    float2 b1;
    if (TRIV) {
        b1 = make_float2(1.f, 0.f);
    } else {
        float sv, cv;
        __sincosf(ang, &sv, &cv);
        b1 = make_float2(cv, SGN < 0 ? -sv : sv);
    }
    float2 b2 = cmul(b1, b1), b4 = cmul(b2, b2), b8 = cmul(b4, b4);
    float2 tw8[8], tw4[4], tw2[2];
#pragma unroll
    for (int k = 0; k < 8; k++) tw8[k] = cmul(b1, rt16<SGN>(k));
#pragma unroll
    for (int k = 0; k < 4; k++) tw4[k] = cmul(b2, rt16<SGN>(2 * k));
    tw2[0] = b4;
    tw2[1] = cmul(b4, make_float2(0.f, (float)SGN));
    if (SGN < 0) {
        if (FIRSTZ) {
#pragma unroll
            for (int k = 0; k < 8; k++) { float2 u = r[k]; r[k + 8] = cmul(u, tw8[k]); }
        } else {
#pragma unroll
            for (int k = 0; k < 8; k++) { float2 u = r[k], v = r[k + 8]; r[k] = cadd(u, v); r[k + 8] = cmul(csub(u, v), tw8[k]); }
        }
#pragma unroll
        for (int g = 0; g < 16; g += 8)
#pragma unroll
            for (int c = 0; c < 4; c++) { int a = g + c; float2 u = r[a], v = r[a + 4]; r[a] = cadd(u, v); r[a + 4] = cmul(csub(u, v), tw4[c]); }
#pragma unroll
        for (int g = 0; g < 16; g += 4)
#pragma unroll
            for (int c = 0; c < 2; c++) { int a = g + c; float2 u = r[a], v = r[a + 2]; r[a] = cadd(u, v); r[a + 2] = cmul(csub(u, v), tw2[c]); }
#pragma unroll
        for (int a = 0; a < 16; a += 2) { float2 u = r[a], v = r[a + 1]; r[a] = cadd(u, v); r[a + 1] = cmul(csub(u, v), b8); }
    } else {
#pragma unroll
        for (int a = 0; a < 16; a += 2) { float2 v = cmul(r[a + 1], b8), u = r[a]; r[a] = cadd(u, v); r[a + 1] = csub(u, v); }
#pragma unroll
        for (int g = 0; g < 16; g += 4)
#pragma unroll
            for (int c = 0; c < 2; c++) { int a = g + c; float2 v = cmul(r[a + 2], tw2[c]), u = r[a]; r[a] = cadd(u, v); r[a + 2] = csub(u, v); }
#pragma unroll
        for (int g = 0; g < 16; g += 8)
#pragma unroll
            for (int c = 0; c < 4; c++) { int a = g + c; float2 v = cmul(r[a + 4], tw4[c]), u = r[a]; r[a] = cadd(u, v); r[a + 4] = csub(u, v); }
#pragma unroll
        for (int k = 0; k < 8; k++) {
            float2 v = cmul(r[k + 8], tw8[k]), u = r[k];
            r[k] = cadd(u, v);
            if (!LASTHALF) r[k + 8] = csub(u, v);
        }
    }
}

// ---------------- K1: (alpha, beta) table per (h, d), natural order ----------------
__global__ __launch_bounds__(256) void k1_spectra(const float* __restrict__ zero,
                                                  const float* __restrict__ pos,
                                                  const float* __restrict__ gamma) {
    __shared__ float2 sm[SMEM_CNT];
    int tid = threadIdx.x;
    int ch = blockIdx.x;          // h*64 + d
    int h = ch >> 6, d = ch & 63;
    float lg = logf(gamma[ch]);
    float e0 = expf(fminf(fmaxf(zero[ch], -60.f), 30.f));

    float2 r[16];
#pragma unroll
    for (int k = 0; k < 16; k++) {
        int m = tid + 256 * k;
        float v0 = 0.f, v1 = 0.f;
        if (k < 8) {
            int t0 = 2 * m, t1 = 2 * m + 1;
            if (t0 == 0) v0 = e0;
            else {
                float p = pos[((size_t)h * 4095 + (t0 - 1)) * 64 + d];
                v0 = expf(fminf(fmaxf(fmaf((float)t0, lg, p), -60.f), 30.f));
            }
            if (t1 <= 4095) {
                float p = pos[((size_t)h * 4095 + (t1 - 1)) * 64 + d];
                v1 = expf(fminf(fmaxf(fmaf((float)t1, lg, p), -60.f), 30.f));
            }
        } else if (m == 2048) {
            v0 = e0;  // a[4096] = exp(clip(zero))
        }
        r[k] = make_float2(v0, v1);
    }

    // forward 4096-pt FFT (natural -> bit-rev)
    fft_round<-1, false>(r, PI_F * (1.0f / 2048.0f) * (float)tid);
#pragma unroll
    for (int k = 0; k < 16; k++) sm[pidx(tid + 256 * k)] = r[k];
    __syncthreads();
    {
        int w = tid & 15, blk = tid >> 4;
#pragma unroll
        for (int k = 0; k < 16; k++) r[k] = sm[pidx(blk * 256 + w + 16 * k)];
        fft_round<-1, false>(r, PI_F * (1.0f / 128.0f) * (float)w);
#pragma unroll
        for (int k = 0; k < 16; k++) sm[pidx(blk * 256 + w + 16 * k)] = r[k];
    }
    __syncthreads();
#pragma unroll
    for (int k = 0; k < 16; k++) r[k] = sm[pidx(tid * 16 + k)];
    fft_round<-1, true>(r, 0.f);
#pragma unroll
    for (int k = 0; k < 16; k++) sm[pidx(tid * 16 + k)] = r[k];
    __syncthreads();

    // Unpack real-FFT: A[kf], scaled by 1/32768; keep Nyquist locally (thread m==0).
    const float sc = 1.0f / 32768.0f;
    float2 ar[16];
    float anyq = 0.f;
#pragma unroll
    for (int k = 0; k < 16; k++) {
        int m = tid + 256 * k;
        int kf = __brev(m) >> 20;
        int mp = __brev((4096 - kf) & 4095) >> 20;
        float2 Zm = sm[pidx(m)], Zp = sm[pidx(mp)];
        float2 S = cadd(Zm, cconj(Zp));
        float2 D = csub(Zm, cconj(Zp));
        float sw, cw;
        __sincosf(PI_F * (1.0f / 4096.0f) * (float)kf, &sw, &cw);
        float2 W = make_float2(cw, -sw);
        float2 T = cmul(W, D);
        float2 T2 = make_float2(T.y, -T.x);       // -i*W*D
        float2 Vlo = cadd(S, T2);                 // = 2*A[kf]
        ar[k] = make_float2(Vlo.x * sc, Vlo.y * sc);
        if (m == 0) {
            float2 Vhi = csub(S, T2);             // = 2*A[4096] (real)
            anyq = Vhi.x * sc;
        }
    }
    __syncthreads();
#pragma unroll
    for (int k = 0; k < 16; k++) sm[pidx(tid + 256 * k)] = ar[k];
    __syncthreads();

    // alpha/beta: Z'[m] = alpha*Z[m] + beta*conj(Z[mp]); natural ab[m] (coalesced).
    float4* ab = g_AB + (size_t)ch * 4096;
#pragma unroll
    for (int k = 0; k < 16; k++) {
        int m = tid + 256 * k;
        int kf = __brev(m) >> 20;
        int mp = __brev((4096 - kf) & 4095) >> 20;
        float2 Alo = sm[pidx(m)];
        float2 Ahi = (m == 0) ? make_float2(anyq, 0.f) : cconj(sm[pidx(mp)]);
        float sw, cw;
        __sincosf(PI_F * (1.0f / 4096.0f) * (float)kf, &sw, &cw);
        float ca = 2.f - 2.f * sw, cb = 2.f + 2.f * sw, cc = 2.f * cw;
        float2 alpha = make_float2(ca * Alo.x + cb * Ahi.x, ca * Alo.y + cb * Ahi.y);
        float2 dif = csub(Alo, Ahi);
        float2 beta = make_float2(-cc * dif.y, cc * dif.x);
        ab[m] = make_float4(alpha.x, alpha.y, beta.x, beta.y);
    }
}

// ---------------- K2: x [bh][t][d] -> g_xt [bh][d][t], 64x64 float4 tiles ----------------
__global__ __launch_bounds__(256) void k2_transpose(const float* __restrict__ x, int bh0) {
    __shared__ float tile[64][65];
    int bh = bh0 + blockIdx.y;
    int t0 = blockIdx.x << 6;
    const float4* xp4 = (const float4*)(x + (size_t)bh * (4096 * 64));
    float4* xtp4 = (float4*)(g_xt + (size_t)bh * (64 * 4096));
    int tx = threadIdx.x & 15, ty = threadIdx.x >> 4;
#pragma unroll
    for (int j = 0; j < 4; j++) {
        int t = ty + 16 * j;
        float4 v = xp4[(size_t)(t0 + t) * 16 + tx];
        tile[t][4 * tx + 0] = v.x; tile[t][4 * tx + 1] = v.y;
        tile[t][4 * tx + 2] = v.z; tile[t][4 * tx + 3] = v.w;
    }
    __syncthreads();
#pragma unroll
    for (int j = 0; j < 4; j++) {
        int d = ty + 16 * j;
        float4 v = make_float4(tile[4 * tx + 0][d], tile[4 * tx + 1][d],
                               tile[4 * tx + 2][d], tile[4 * tx + 3][d]);
        xtp4[(size_t)d * 1024 + (t0 >> 2) + tx] = v;
    }
}

// ---------------- K3: per (b, h, d) real FFT conv; folded-immediate mid indices ----------------
__global__ __launch_bounds__(256, 3) void k3_fftconv(int b0) {
    __shared__ float2 sm[SMEM_CNT];
    int tid = threadIdx.x;
    // Block order: idx = hd*4 + (b - b0): 4 batch-blocks sharing one AB row adjacent (L2 reuse).
    int idx = blockIdx.x;
    int b  = b0 + (idx & 3);
    int hd = idx >> 2;                 // ch = h*64 + d
    int bhd = (b * 8 + (hd >> 6)) * 64 + (hd & 63);
    float2* row = (float2*)(g_xt + (size_t)bhd * 4096);

    float2 r[16];
#pragma unroll
    for (int k = 0; k < 8; k++) r[k] = row[tid + 256 * k];      // z[m]=u[2m]+i u[2m+1]
#pragma unroll
    for (int k = 8; k < 16; k++) r[k] = make_float2(0.f, 0.f);  // zero padding

    // forward rounds (round 1 exploits zero upper half)
    fft_round<-1, false, true>(r, PI_F * (1.0f / 2048.0f) * (float)tid);
#pragma unroll
    for (int k = 0; k < 16; k++) sm[pidx(tid + 256 * k)] = r[k];
    __syncthreads();
    int w = tid & 15, blk = tid >> 4;
#pragma unroll
    for (int k = 0; k < 16; k++) r[k] = sm[pidx(blk * 256 + w + 16 * k)];
    fft_round<-1, false>(r, PI_F * (1.0f / 128.0f) * (float)w);
#pragma unroll
    for (int k = 0; k < 16; k++) sm[pidx(blk * 256 + w + 16 * k)] = r[k];
    __syncthreads();
#pragma unroll
    for (int k = 0; k < 16; k++) r[k] = sm[pidx(tid * 16 + k)];
    fft_round<-1, true>(r, 0.f);
#pragma unroll
    for (int k = 0; k < 16; k++) sm[pidx(tid * 16 + k)] = r[k];
    __syncthreads();

    // MID: Z'[m] = alpha*Z[m] + beta*conj(Z[mp]), m = tid + 256k.
    // Folded partner index: for k>=1, mp = 256*ck + (255 - tid) with ck from a
    // compile-time table, so pidx(mp) = 272*ck + pidx(255 - tid) — immediates.
    // (Derivation: kf = 16*brev8(tid) + brev4(k); 4096-kf = 16*(255-brev8(tid)) +
    //  (16-brev4(k)); brev12 of that = 256*brev4(16-brev4(k)) + (255-tid).)
    // k = 0: mp0 = brev8((256 - brev8(tid)) & 255), per-thread.
    const float4* abp = g_AB + (size_t)hd * 4096;
    static const int CK[16] = {0, 1, 3, 2, 7, 6, 5, 4, 15, 14, 13, 12, 11, 10, 9, 8};
    int S = 255 - tid;
    int QP = S + (S >> 4);                                      // pidx(255 - tid)
    int mp0 = __brev((256 - (__brev(tid) >> 24)) & 255) >> 24;
    int QP0 = mp0 + (mp0 >> 4);                                 // pidx(mp0)
    int Qm = tid + (tid >> 4);                                  // pidx(tid)
#pragma unroll
    for (int k = 0; k < 16; k++) {
        float2 Zm = sm[Qm + 272 * k];                           // pidx(tid + 256k)
        float2 Zp = sm[(k == 0) ? QP0 : (QP + 272 * CK[k])];    // pidx(mp)
        float4 ab = abp[tid + 256 * k];
        float2 t1 = cmul(Zm, make_float2(ab.x, ab.y));
        float2 t2 = cmul(cconj(Zp), make_float2(ab.z, ab.w));
        r[k] = cadd(t1, t2);
    }
    __syncthreads();
#pragma unroll
    for (int k = 0; k < 16; k++) sm[Qm + 272 * k] = r[k];
    __syncthreads();

    // Inverse DIT (bit-rev -> natural), mirrored rounds.
#pragma unroll
    for (int k = 0; k < 16; k++) r[k] = sm[pidx(tid * 16 + k)];
    fft_round<1, true>(r, 0.f);
#pragma unroll
    for (int k = 0; k < 16; k++) sm[pidx(tid * 16 + k)] = r[k];
    __syncthreads();
#pragma unroll
    for (int k = 0; k < 16; k++) r[k] = sm[pidx(blk * 256 + w + 16 * k)];
    fft_round<1, false>(r, PI_F * (1.0f / 128.0f) * (float)w);
#pragma unroll
    for (int k = 0; k < 16; k++) sm[pidx(blk * 256 + w + 16 * k)] = r[k];
    __syncthreads();
#pragma unroll
    for (int k = 0; k < 16; k++) r[k] = sm[pidx(tid + 256 * k)];
    fft_round<1, false, false, true>(r, PI_F * (1.0f / 2048.0f) * (float)tid);
#pragma unroll
    for (int k = 0; k < 8; k++) row[tid + 256 * k] = r[k];   // y[2m], y[2m+1]; t<4096 only
}

// ---------------- K4: g_xt (y) [bh][d][t] -> out [bh][t][d], 64x64 float4 tiles ----------------
__global__ __launch_bounds__(256) void k4_transpose(float* __restrict__ out, int bh0) {
    __shared__ float tile[64][65];
    int bh = bh0 + blockIdx.y;
    int t0 = blockIdx.x << 6;
    const float4* ytp4 = (const float4*)(g_xt + (size_t)bh * (64 * 4096));
    float4* op4 = (float4*)(out + (size_t)bh * (4096 * 64));
    int tx = threadIdx.x & 15, ty = threadIdx.x >> 4;
#pragma unroll
    for (int j = 0; j < 4; j++) {
        int d = ty + 16 * j;
        float4 v = ytp4[(size_t)d * 1024 + (t0 >> 2) + tx];
        tile[4 * tx + 0][d] = v.x; tile[4 * tx + 1][d] = v.y;
        tile[4 * tx + 2][d] = v.z; tile[4 * tx + 3][d] = v.w;
    }
    __syncthreads();
#pragma unroll
    for (int j = 0; j < 4; j++) {
        int t = ty + 16 * j;
        float4 v = make_float4(tile[t][4 * tx + 0], tile[t][4 * tx + 1],
                               tile[t][4 * tx + 2], tile[t][4 * tx + 3]);
        op4[(size_t)(t0 + t) * 16 + tx] = v;
    }
}

// ---- streams/events for pipelined graph topology (R12 half-split DAG) ----
static cudaStream_t g_s2 = 0, g_s3 = 0;
static cudaEvent_t g_evRoot = 0, g_evK1 = 0, g_evK3a = 0, g_evK3b = 0;
static bool g_ok = false;
static struct StreamInit {
    StreamInit() {
        bool ok = true;
        ok &= cudaStreamCreateWithFlags(&g_s2, cudaStreamNonBlocking) == cudaSuccess;
        ok &= cudaStreamCreateWithFlags(&g_s3, cudaStreamNonBlocking) == cudaSuccess;
        ok &= cudaEventCreateWithFlags(&g_evRoot, cudaEventDisableTiming) == cudaSuccess;
        ok &= cudaEventCreateWithFlags(&g_evK1, cudaEventDisableTiming) == cudaSuccess;
        ok &= cudaEventCreateWithFlags(&g_evK3a, cudaEventDisableTiming) == cudaSuccess;
        ok &= cudaEventCreateWithFlags(&g_evK3b, cudaEventDisableTiming) == cudaSuccess;
        g_ok = ok;
    }
} g_stream_init;

extern "C" void kernel_launch(void* const* d_in, const int* in_sizes, int n_in,
                              void* d_out, int out_size) {
    (void)in_sizes; (void)n_in; (void)out_size;
    const float* x     = (const float*)d_in[0];
    const float* zero  = (const float*)d_in[1];
    const float* pos   = (const float*)d_in[2];
    const float* gamma = (const float*)d_in[3];
    float* out = (float*)d_out;

    if (g_ok) {
        cudaEventRecord(g_evRoot, 0);
        cudaStreamWaitEvent(g_s2, g_evRoot, 0);
        cudaStreamWaitEvent(g_s3, g_evRoot, 0);

        k1_spectra<<<512, 256, 0, g_s2>>>(zero, pos, gamma);
        cudaEventRecord(g_evK1, g_s2);

        k2_transpose<<<dim3(64, 32), 256, 0, g_s3>>>(x, 32);   // bh 32..63
        k2_transpose<<<dim3(64, 32), 256>>>(x, 0);             // bh 0..31

        cudaStreamWaitEvent(0, g_evK1, 0);
        k3_fftconv<<<2048, 256>>>(0);                          // b 0..3
        cudaEventRecord(g_evK3a, 0);

        cudaStreamWaitEvent(g_s3, g_evK1, 0);
        cudaStreamWaitEvent(g_s3, g_evK3a, 0);
        k3_fftconv<<<2048, 256, 0, g_s3>>>(4);                 // b 4..7
        cudaEventRecord(g_evK3b, g_s3);

        k4_transpose<<<dim3(64, 32), 256>>>(out, 0);           // overlaps K3b

        cudaStreamWaitEvent(0, g_evK3b, 0);
        k4_transpose<<<dim3(64, 32), 256>>>(out, 32);
    } else {
        k1_spectra<<<512, 256>>>(zero, pos, gamma);
        k2_transpose<<<dim3(64, 32), 256>>>(x, 0);
        k2_transpose<<<dim3(64, 32), 256>>>(x, 32);
        k3_fftconv<<<2048, 256>>>(0);
        k3_fftconv<<<2048, 256>>>(4);
        k4_transpose<<<dim3(64, 32), 256>>>(out, 0);
        k4_transpose<<<dim3(64, 32), 256>>>(out, 32);
    }
}